// round 6
// baseline (speedup 1.0000x reference)
#include <cuda_runtime.h>
#include <cuda_bf16.h>
#include <cstdint>

// GGMLLinear: out[o] = sum_k x[k] * scales[o, k/32] * q[o,k] + bias[o]
// x: [1, 4096] f32, q: [14336, 4096] int32 (int8-range), scales: [14336, 128] f32,
// bias: [14336] f32, out: [1, 14336] f32.
//
// Memory-bound GEMV (235MB q stream). R6: cp.async.cg pipeline.
// In-flight bytes were register-limited (R5: regs 40->48 lifted DRAM 73.9->78.3%).
// LDGSTS holds no registers and no scoreboard slot -> per-lane 4-stage smem ring
// of its OWN 16B slots (issuing thread may read its own cp-async data after
// wait_group, no CTA barrier). 32KB smem/CTA -> 7 CTAs/SM, 56 warps,
// in-flight = 56 x 2KB = 112KB/SM >> ~20KB Little's-law requirement.
// .cg bypasses L1 (pure stream). Scales via R5's reg+shuffle scheme.

#define IN_DIM 4096
#define OUT_DIM 14336
#define NB (IN_DIM / 32)          // 128 scale blocks per row
#define ROWS_PER_CTA 8
#define THREADS 256
#define STAGES 4                  // per-lane pipeline depth (16B per stage)

__device__ __forceinline__ uint32_t smem_u32(const void* p) {
    uint32_t a;
    asm("{ .reg .u64 t; cvta.to.shared.u64 t, %1; cvt.u32.u64 %0, t; }"
        : "=r"(a) : "l"(p));
    return a;
}

__device__ __forceinline__ void cp_async16(uint32_t dst, const void* src) {
    asm volatile("cp.async.cg.shared.global [%0], [%1], 16;"
                 :: "r"(dst), "l"(src));
}

__device__ __forceinline__ void cp_commit() {
    asm volatile("cp.async.commit_group;");
}

template <int N>
__device__ __forceinline__ void cp_wait() {
    asm volatile("cp.async.wait_group %0;" :: "n"(N));
}

__global__ __launch_bounds__(THREADS)
void ggml_q8_gemv(const float* __restrict__ x,
                  const int* __restrict__ q,
                  const float* __restrict__ scales,
                  const float* __restrict__ bias,
                  float* __restrict__ out)
{
    __shared__ float xs[IN_DIM];                                   // 16KB
    __shared__ __align__(16) int4 qbuf[ROWS_PER_CTA][STAGES][32];  // 16KB

    // Stage x (16KB) into shared. 1024 float4 / 256 threads = 4 each.
    {
        const float4* x4 = reinterpret_cast<const float4*>(x);
        float4* xs4 = reinterpret_cast<float4*>(xs);
        #pragma unroll
        for (int i = threadIdx.x; i < IN_DIM / 4; i += THREADS)
            xs4[i] = x4[i];
    }
    __syncthreads();

    const int warp = threadIdx.x >> 5;
    const int lane = threadIdx.x & 31;
    const int row  = blockIdx.x * ROWS_PER_CTA + warp;   // grid sized exactly

    const int4*   qrow = reinterpret_cast<const int4*>(q + (size_t)row * IN_DIM);
    const float4* xs4  = reinterpret_cast<const float4*>(xs);

    // This lane's private ring: qbuf[warp][s][lane], s = 0..STAGES-1.
    const uint32_t ring = smem_u32(&qbuf[warp][0][lane]);
    const uint32_t ring_stride = 32 * sizeof(int4);   // stage stride = 512B

    // Preload all 128 row scales, strided: lane L holds scale[L + 32*r].
    const float* srow = scales + (size_t)row * NB;
    const float s0 = __ldg(&srow[lane]);
    const float s1 = __ldg(&srow[lane + 32]);
    const float s2 = __ldg(&srow[lane + 64]);
    const float s3 = __ldg(&srow[lane + 96]);
    const int csel = lane >> 3;

    // Pipeline prologue: fill STAGES stages, one commit-group per stage.
    #pragma unroll
    for (int s = 0; s < STAGES; ++s) {
        cp_async16(ring + s * ring_stride, &qrow[s * 32 + lane]);
        cp_commit();
    }

    float acc = 0.0f;

    // 32 iterations; iteration it consumes stage it%STAGES (filled by group #it),
    // then refills that stage for iteration it+STAGES and commits one group.
    // wait_group(STAGES-1) at iter it drains exactly through group #it.
    #pragma unroll
    for (int it = 0; it < 32; ++it) {
        cp_wait<STAGES - 1>();
        const int stage = it & (STAGES - 1);
        int4 qv;
        {
            const uint32_t a = ring + stage * ring_stride;
            asm volatile("ld.shared.v4.b32 {%0,%1,%2,%3}, [%4];"
                         : "=r"(qv.x), "=r"(qv.y), "=r"(qv.z), "=r"(qv.w)
                         : "r"(a));
        }
        const float4 xv = xs4[it * 32 + lane];
        const float  sv = (it < 8) ? s0 : (it < 16) ? s1 : (it < 24) ? s2 : s3;
        const float  s  = __shfl_sync(0xffffffffu, sv, ((it & 7) << 2) + csel);

        float dot = xv.x * (float)qv.x;
        dot = fmaf(xv.y, (float)qv.y, dot);
        dot = fmaf(xv.z, (float)qv.z, dot);
        dot = fmaf(xv.w, (float)qv.w, dot);
        acc = fmaf(s, dot, acc);

        const int nxt = it + STAGES;
        if (nxt < 32)
            cp_async16(ring + stage * ring_stride, &qrow[nxt * 32 + lane]);
        cp_commit();   // one group per iteration keeps accounting exact
    }

    // Warp reduction
    #pragma unroll
    for (int off = 16; off > 0; off >>= 1)
        acc += __shfl_xor_sync(0xffffffffu, acc, off);

    if (lane == 0)
        out[row] = acc + __ldg(&bias[row]);
}

extern "C" void kernel_launch(void* const* d_in, const int* in_sizes, int n_in,
                              void* d_out, int out_size)
{
    const float* x      = (const float*)d_in[0];
    const int*   q      = (const int*)d_in[1];
    const float* scales = (const float*)d_in[2];
    const float* bias   = (const float*)d_in[3];
    float*       out    = (float*)d_out;

    const int grid = OUT_DIM / ROWS_PER_CTA;   // 1792
    ggml_q8_gemv<<<grid, THREADS>>>(x, q, scales, bias, out);
}

// round 7
// speedup vs baseline: 1.1032x; 1.1032x over previous
#include <cuda_runtime.h>
#include <cuda_bf16.h>

// GGMLLinear: out[o] = sum_k x[k] * scales[o, k/32] * q[o,k] + bias[o]
// x: [1, 4096] f32, q: [14336, 4096] int32 (int8-range), scales: [14336, 128] f32,
// bias: [14336] f32, out: [1, 14336] f32.
//
// Memory-bound GEMV (235MB q stream). R7: 2 rows per warp.
// R6 showed the smem crossbar binds when q moves 48B/cyc of smem traffic per
// 16B of q; direct-LDG q + one shared x read per 32B of q halves x crossbar
// traffic, doubles front-batched LDGs per warp (2 independent row streams),
// and halves loop/shuffle/reduction overhead per q byte.
// Scales via the proven strided-register + shuffle scheme (per row).

#define IN_DIM 4096
#define OUT_DIM 14336
#define NB (IN_DIM / 32)          // 128 scale blocks per row
#define ROWS_PER_CTA 16           // 8 warps x 2 rows
#define THREADS 256

__global__ __launch_bounds__(THREADS, 4)
void ggml_q8_gemv(const float* __restrict__ x,
                  const int* __restrict__ q,
                  const float* __restrict__ scales,
                  const float* __restrict__ bias,
                  float* __restrict__ out)
{
    __shared__ float xs[IN_DIM];

    // Stage x (16KB) into shared. 1024 float4 / 256 threads = 4 each.
    {
        const float4* x4 = reinterpret_cast<const float4*>(x);
        float4* xs4 = reinterpret_cast<float4*>(xs);
        #pragma unroll
        for (int i = threadIdx.x; i < IN_DIM / 4; i += THREADS)
            xs4[i] = x4[i];
    }
    __syncthreads();

    const int warp = threadIdx.x >> 5;
    const int lane = threadIdx.x & 31;
    const int rowA = blockIdx.x * ROWS_PER_CTA + warp * 2;   // grid sized exactly
    const int rowB = rowA + 1;

    const int4*   qrowA = reinterpret_cast<const int4*>(q + (size_t)rowA * IN_DIM);
    const int4*   qrowB = reinterpret_cast<const int4*>(q + (size_t)rowB * IN_DIM);
    const float4* xs4   = reinterpret_cast<const float4*>(xs);

    // Preload all 128 scales per row, strided: lane L holds scale[L + 32*r].
    // Scale for iter it, lane L: scale[4*it + (L>>3)]
    //   = reg (it>>3) of lane ((it&7)*4 + (L>>3)).
    const float* srowA = scales + (size_t)rowA * NB;
    const float* srowB = scales + (size_t)rowB * NB;
    const float a0 = __ldg(&srowA[lane]);
    const float a1 = __ldg(&srowA[lane + 32]);
    const float a2 = __ldg(&srowA[lane + 64]);
    const float a3 = __ldg(&srowA[lane + 96]);
    const float b0 = __ldg(&srowB[lane]);
    const float b1 = __ldg(&srowB[lane + 32]);
    const float b2 = __ldg(&srowB[lane + 64]);
    const float b3 = __ldg(&srowB[lane + 96]);
    const int csel = lane >> 3;

    float accA = 0.0f;
    float accB = 0.0f;

    // 1024 int4 per row / 32 lanes = 32 steps. idx4 = it*32 + lane.
    #pragma unroll 4
    for (int it = 0; it < 32; ++it) {
        const int idx4 = it * 32 + lane;
        const int4   qa = __ldg(&qrowA[idx4]);
        const int4   qb = __ldg(&qrowB[idx4]);
        const float4 xv = xs4[idx4];
        const int    src = ((it & 7) << 2) + csel;
        const float  sva = (it < 8) ? a0 : (it < 16) ? a1 : (it < 24) ? a2 : a3;
        const float  svb = (it < 8) ? b0 : (it < 16) ? b1 : (it < 24) ? b2 : b3;
        const float  sA = __shfl_sync(0xffffffffu, sva, src);
        const float  sB = __shfl_sync(0xffffffffu, svb, src);

        float dA = xv.x * (float)qa.x;
        dA = fmaf(xv.y, (float)qa.y, dA);
        dA = fmaf(xv.z, (float)qa.z, dA);
        dA = fmaf(xv.w, (float)qa.w, dA);
        accA = fmaf(sA, dA, accA);

        float dB = xv.x * (float)qb.x;
        dB = fmaf(xv.y, (float)qb.y, dB);
        dB = fmaf(xv.z, (float)qb.z, dB);
        dB = fmaf(xv.w, (float)qb.w, dB);
        accB = fmaf(sB, dB, accB);
    }

    // Warp reductions
    #pragma unroll
    for (int off = 16; off > 0; off >>= 1) {
        accA += __shfl_xor_sync(0xffffffffu, accA, off);
        accB += __shfl_xor_sync(0xffffffffu, accB, off);
    }

    if (lane == 0) {
        out[rowA] = accA + __ldg(&bias[rowA]);
        out[rowB] = accB + __ldg(&bias[rowB]);
    }
}

extern "C" void kernel_launch(void* const* d_in, const int* in_sizes, int n_in,
                              void* d_out, int out_size)
{
    const float* x      = (const float*)d_in[0];
    const int*   q      = (const int*)d_in[1];
    const float* scales = (const float*)d_in[2];
    const float* bias   = (const float*)d_in[3];
    float*       out    = (float*)d_out;

    const int grid = OUT_DIM / ROWS_PER_CTA;   // 896
    ggml_q8_gemv<<<grid, THREADS>>>(x, q, scales, bias, out);
}

// round 8
// speedup vs baseline: 1.1104x; 1.0065x over previous
#include <cuda_runtime.h>
#include <cuda_bf16.h>

// GGMLLinear: out[o] = sum_k x[k] * scales[o, k/32] * q[o,k] + bias[o]
// x: [1, 4096] f32, q: [14336, 4096] int32 (int8-range), scales: [14336, 128] f32,
// bias: [14336] f32, out: [1, 14336] f32.
//
// Memory-bound GEMV (235MB q stream). R8: R7's exact per-warp code (2 rows per
// warp, 64 regs, unroll 4, strided-scale shuffle) with HALF the CTA grain:
// 128 threads / 8 rows, grid=1792, 8 CTAs/SM. Same resident warps (32/SM),
// same regs; per-SM tile count goes 6.05/7 -> 12.1/13, shrinking the
// end-of-kernel imbalance tail from ~13% to ~4%. (R3's grain regression was
// confounded by a reg drop 40->32; this isolates grain at constant regs.)

#define IN_DIM 4096
#define OUT_DIM 14336
#define NB (IN_DIM / 32)          // 128 scale blocks per row
#define ROWS_PER_CTA 8            // 4 warps x 2 rows
#define THREADS 128

__global__ __launch_bounds__(THREADS, 8)
void ggml_q8_gemv(const float* __restrict__ x,
                  const int* __restrict__ q,
                  const float* __restrict__ scales,
                  const float* __restrict__ bias,
                  float* __restrict__ out)
{
    __shared__ float xs[IN_DIM];

    // Stage x (16KB) into shared. 1024 float4 / 128 threads = 8 each.
    {
        const float4* x4 = reinterpret_cast<const float4*>(x);
        float4* xs4 = reinterpret_cast<float4*>(xs);
        #pragma unroll
        for (int i = threadIdx.x; i < IN_DIM / 4; i += THREADS)
            xs4[i] = x4[i];
    }
    __syncthreads();

    const int warp = threadIdx.x >> 5;
    const int lane = threadIdx.x & 31;
    const int rowA = blockIdx.x * ROWS_PER_CTA + warp * 2;   // grid sized exactly
    const int rowB = rowA + 1;

    const int4*   qrowA = reinterpret_cast<const int4*>(q + (size_t)rowA * IN_DIM);
    const int4*   qrowB = reinterpret_cast<const int4*>(q + (size_t)rowB * IN_DIM);
    const float4* xs4   = reinterpret_cast<const float4*>(xs);

    // Preload all 128 scales per row, strided: lane L holds scale[L + 32*r].
    // Scale for iter it, lane L: scale[4*it + (L>>3)]
    //   = reg (it>>3) of lane ((it&7)*4 + (L>>3)).
    const float* srowA = scales + (size_t)rowA * NB;
    const float* srowB = scales + (size_t)rowB * NB;
    const float a0 = __ldg(&srowA[lane]);
    const float a1 = __ldg(&srowA[lane + 32]);
    const float a2 = __ldg(&srowA[lane + 64]);
    const float a3 = __ldg(&srowA[lane + 96]);
    const float b0 = __ldg(&srowB[lane]);
    const float b1 = __ldg(&srowB[lane + 32]);
    const float b2 = __ldg(&srowB[lane + 64]);
    const float b3 = __ldg(&srowB[lane + 96]);
    const int csel = lane >> 3;

    float accA = 0.0f;
    float accB = 0.0f;

    // 1024 int4 per row / 32 lanes = 32 steps. idx4 = it*32 + lane.
    #pragma unroll 4
    for (int it = 0; it < 32; ++it) {
        const int idx4 = it * 32 + lane;
        const int4   qa = __ldg(&qrowA[idx4]);
        const int4   qb = __ldg(&qrowB[idx4]);
        const float4 xv = xs4[idx4];
        const int    src = ((it & 7) << 2) + csel;
        const float  sva = (it < 8) ? a0 : (it < 16) ? a1 : (it < 24) ? a2 : a3;
        const float  svb = (it < 8) ? b0 : (it < 16) ? b1 : (it < 24) ? b2 : b3;
        const float  sA = __shfl_sync(0xffffffffu, sva, src);
        const float  sB = __shfl_sync(0xffffffffu, svb, src);

        float dA = xv.x * (float)qa.x;
        dA = fmaf(xv.y, (float)qa.y, dA);
        dA = fmaf(xv.z, (float)qa.z, dA);
        dA = fmaf(xv.w, (float)qa.w, dA);
        accA = fmaf(sA, dA, accA);

        float dB = xv.x * (float)qb.x;
        dB = fmaf(xv.y, (float)qb.y, dB);
        dB = fmaf(xv.z, (float)qb.z, dB);
        dB = fmaf(xv.w, (float)qb.w, dB);
        accB = fmaf(sB, dB, accB);
    }

    // Warp reductions
    #pragma unroll
    for (int off = 16; off > 0; off >>= 1) {
        accA += __shfl_xor_sync(0xffffffffu, accA, off);
        accB += __shfl_xor_sync(0xffffffffu, accB, off);
    }

    if (lane == 0) {
        out[rowA] = accA + __ldg(&bias[rowA]);
        out[rowB] = accB + __ldg(&bias[rowB]);
    }
}

extern "C" void kernel_launch(void* const* d_in, const int* in_sizes, int n_in,
                              void* d_out, int out_size)
{
    const float* x      = (const float*)d_in[0];
    const int*   q      = (const int*)d_in[1];
    const float* scales = (const float*)d_in[2];
    const float* bias   = (const float*)d_in[3];
    float*       out    = (float*)d_out;

    const int grid = OUT_DIM / ROWS_PER_CTA;   // 1792
    ggml_q8_gemv<<<grid, THREADS>>>(x, q, scales, bias, out);
}